// round 4
// baseline (speedup 1.0000x reference)
#include <cuda_runtime.h>

// ---------------------------------------------------------------------------
// PyramidAttention (UrbanODE core), B=32, C=64, H=W=32, 5 scales, N=3278.
//
//   S[m,q]      = sum_c refm[c,m] * match[c,q]              (K=32 GEMM)
//   logit[n,p]  = 10*invnorm[n] * sum_d S[n+d, p+d]         (9-tap diag stencil)
//   yn          = softmax over n (per (b,p))                <- fused, row in smem
//   T[p,m]      = sum_d yn[m+d, p+d]                        <- fused into GEMM2 B-load
//   out[c,p]    = x[c,p] + 0.25 * sum_m base[c,m] * T[p,m]  (K=3278 GEMM)
// ---------------------------------------------------------------------------

namespace {
constexpr int kB  = 32;
constexpr int kC  = 64;
constexpr int kC2 = 32;
constexpr int kHW = 1024;
constexpr int kN  = 3278;   // 1024+784+625+484+361
constexpr int kNS = 3280;   // padded row stride
}

// scratch (device globals: allocation-free rule)
__device__ float  g_match[(size_t)kB * kC2 * kHW];
__device__ float  g_refm [(size_t)kB * kC2 * kN];
__device__ float  g_base [(size_t)kB * kC  * kN];
__device__ float  g_sq   [(size_t)kB * kN];
__device__ float  g_invn [(size_t)kB * kN];
__device__ float  g_buf1 [(size_t)kB * kHW * kNS];  // S
__device__ float  g_buf2 [(size_t)kB * kHW * kNS];  // yn

// pyramid pixel -> (level-local y, x, level width). levels are square.
__device__ __forceinline__ void n_geom(int n, int& ny, int& nx, int& wl)
{
    if (n < 1024)      { int loc = n;        ny = loc >> 5;  nx = loc & 31;     wl = 32; }
    else if (n < 1808) { int loc = n - 1024; ny = loc / 28;  nx = loc - ny*28;  wl = 28; }
    else if (n < 2433) { int loc = n - 1808; ny = loc / 25;  nx = loc - ny*25;  wl = 25; }
    else if (n < 2917) { int loc = n - 2433; ny = loc / 22;  nx = loc - ny*22;  wl = 22; }
    else               { int loc = n - 2917; ny = loc / 19;  nx = loc - ny*19;  wl = 19; }
}

// ---------------------------------------------------------------------------
// match_base = prelu(conv1x1(x, w_base)) : [B,32,1024]
// ---------------------------------------------------------------------------
__global__ __launch_bounds__(256) void k_conv_main(
    const float* __restrict__ x, const float* __restrict__ w,
    const float* __restrict__ bias, const float* __restrict__ a)
{
    int t = blockIdx.x * blockDim.x + threadIdx.x;
    if (t >= kB * kC2 * kHW) return;
    int p  = t & (kHW - 1);
    int co = (t >> 10) & 31;
    int b  = t >> 15;
    const float* xb = x + ((size_t)b * kC) * kHW + p;
    const float* wr = w + co * kC;
    float acc = bias[co];
#pragma unroll
    for (int c = 0; c < kC; c++) acc = fmaf(wr[c], xb[(size_t)c * kHW], acc);
    float al = a[0];
    g_match[t] = acc >= 0.f ? acc : al * acc;
}

// ---------------------------------------------------------------------------
// pyramid conv1x1 + prelu (nearest-resize folded into indexing).
// DST=0 -> g_refm (also writes g_sq = sum of squares), DST=1 -> g_base.
// ---------------------------------------------------------------------------
template <int COUT, int DST>
__global__ __launch_bounds__(256) void k_conv_pyr(
    const float* __restrict__ x, const float* __restrict__ w,
    const float* __restrict__ bias, const float* __restrict__ a)
{
    __shared__ float ws[COUT * kC];
    for (int i = threadIdx.x; i < COUT * kC; i += 256) ws[i] = w[i];
    __syncthreads();

    int n = blockIdx.x * 256 + threadIdx.x;
    int b = blockIdx.y;
    if (n >= kN) return;

    int ny, nx, wl;
    n_geom(n, ny, nx, wl);
    int sy = (ny * 32) / wl;
    int sx = (nx * 32) / wl;
    const float* xb = x + ((size_t)b * kC) * kHW + sy * 32 + sx;

    float acc[COUT];
#pragma unroll
    for (int co = 0; co < COUT; co++) acc[co] = bias[co];
#pragma unroll 4
    for (int c = 0; c < kC; c++) {
        float xv = xb[(size_t)c * kHW];
#pragma unroll
        for (int co = 0; co < COUT; co++) acc[co] = fmaf(ws[co * kC + c], xv, acc[co]);
    }
    float al = a[0];
    float* ob = (DST == 0 ? g_refm : g_base) + (size_t)b * COUT * kN + n;
    float sq = 0.f;
#pragma unroll
    for (int co = 0; co < COUT; co++) {
        float v = acc[co];
        v = v >= 0.f ? v : al * v;
        ob[(size_t)co * kN] = v;
        sq = fmaf(v, v, sq);
    }
    if (DST == 0) g_sq[(size_t)b * kN + n] = sq;
}

// invnorm[n] = 10 / max(sqrt(sum_{valid d} sq[n+d]), 1e-4)
__global__ __launch_bounds__(256) void k_invn()
{
    int t = blockIdx.x * blockDim.x + threadIdx.x;
    if (t >= kB * kN) return;
    int n = t % kN, b = t / kN;
    int ny, nx, wl;
    n_geom(n, ny, nx, wl);
    const float* sq = g_sq + (size_t)b * kN;
    float s = 0.f;
#pragma unroll
    for (int dy = -1; dy <= 1; dy++) {
        int my = ny + dy;
        if ((unsigned)my >= (unsigned)wl) continue;
#pragma unroll
        for (int dx = -1; dx <= 1; dx++) {
            int mx = nx + dx;
            if ((unsigned)mx >= (unsigned)wl) continue;
            s += sq[n + dy * wl + dx];
        }
    }
    float nr = fmaxf(sqrtf(s), 1e-4f);
    g_invn[t] = 10.f / nr;
}

// ---------------------------------------------------------------------------
// GEMM1: S[b][p][n] = sum_{c<32} match[b][c][p] * refm[b][c][n]
// ---------------------------------------------------------------------------
__global__ __launch_bounds__(256) void k_gemm1()
{
    __shared__ float As[32][65];  // [k][p]
    __shared__ float Bs[32][65];  // [k][n]
    int b  = blockIdx.z;
    int p0 = blockIdx.y * 64;
    int n0 = blockIdx.x * 64;
    const float* Ab = g_match + (size_t)b * kC2 * kHW;
    const float* Bb = g_refm  + (size_t)b * kC2 * kN;
    int tid = threadIdx.x;
#pragma unroll
    for (int i = tid; i < 32 * 64; i += 256) {
        int k = i >> 6, j = i & 63;
        As[k][j] = Ab[(size_t)k * kHW + p0 + j];
        int n = n0 + j;
        Bs[k][j] = (n < kN) ? Bb[(size_t)k * kN + n] : 0.f;
    }
    __syncthreads();
    int tx = tid & 15, ty = tid >> 4;
    float acc[4][4] = {};
#pragma unroll
    for (int k = 0; k < 32; k++) {
        float av[4], bv[4];
#pragma unroll
        for (int r = 0; r < 4; r++) av[r] = As[k][ty + r * 16];
#pragma unroll
        for (int l = 0; l < 4; l++) bv[l] = Bs[k][tx + l * 16];
#pragma unroll
        for (int r = 0; r < 4; r++)
#pragma unroll
            for (int l = 0; l < 4; l++) acc[r][l] = fmaf(av[r], bv[l], acc[r][l]);
    }
    float* Sb = g_buf1 + (size_t)b * kHW * kNS;
#pragma unroll
    for (int r = 0; r < 4; r++) {
        int p = p0 + ty + r * 16;
#pragma unroll
        for (int l = 0; l < 4; l++) {
            int n = n0 + tx + l * 16;
            if (n < kN) Sb[(size_t)p * kNS + n] = acc[r][l];
        }
    }
}

// ---------------------------------------------------------------------------
// FUSED: logits (9-tap stencil of S, scaled by invnorm) + row softmax -> yn.
// One block per (p, b); the whole 3278-logit row lives in smem.
// ---------------------------------------------------------------------------
__global__ __launch_bounds__(256) void k_softmax()
{
    __shared__ float row[kNS];
    __shared__ float red[8];
    int p = blockIdx.x, b = blockIdx.y;
    int tid = threadIdx.x;
    int lane = tid & 31, wid = tid >> 5;
    int py = p >> 5, px = p & 31;
    const float* S    = g_buf1 + (size_t)b * kHW * kNS;
    const float* invn = g_invn + (size_t)b * kN;

    float mx = -3.4e38f;
    for (int n = tid; n < kN; n += 256) {
        int ny, nx, wl;
        n_geom(n, ny, nx, wl);
        float s = 0.f;
#pragma unroll
        for (int dy = -1; dy <= 1; dy++) {
            int qy = py + dy, my = ny + dy;
            if ((unsigned)qy >= 32u || (unsigned)my >= (unsigned)wl) continue;
#pragma unroll
            for (int dx = -1; dx <= 1; dx++) {
                int qx = px + dx, mxx = nx + dx;
                if ((unsigned)qx >= 32u || (unsigned)mxx >= (unsigned)wl) continue;
                s += S[(size_t)(qy * 32 + qx) * kNS + (n + dy * wl + dx)];
            }
        }
        s *= invn[n];
        row[n] = s;
        mx = fmaxf(mx, s);
    }
    // block max
#pragma unroll
    for (int o = 16; o > 0; o >>= 1) mx = fmaxf(mx, __shfl_xor_sync(0xffffffffu, mx, o));
    if (lane == 0) red[wid] = mx;
    __syncthreads();
    mx = red[0];
#pragma unroll
    for (int i = 1; i < 8; i++) mx = fmaxf(mx, red[i]);
    __syncthreads();

    float sum = 0.f;
    for (int n = tid; n < kN; n += 256) {
        float e = __expf(row[n] - mx);
        row[n] = e;
        sum += e;
    }
#pragma unroll
    for (int o = 16; o > 0; o >>= 1) sum += __shfl_xor_sync(0xffffffffu, sum, o);
    if (lane == 0) red[wid] = sum;
    __syncthreads();
    sum = red[0];
#pragma unroll
    for (int i = 1; i < 8; i++) sum += red[i];
    float inv = 1.f / sum;

    float* yn = g_buf2 + ((size_t)b * kHW + p) * kNS;
    for (int n = tid; n < kN; n += 256) yn[n] = row[n] * inv;
}

// ---------------------------------------------------------------------------
// FUSED GEMM2: out[b][c][p] = x[b][c][p] + 0.25 * sum_m base[b][c][m] * T[b][p][m]
// with T computed on the fly in the B-tile loader (9-tap stencil of yn).
// Tile 64c x 256p, BK=32; 256 threads, 8x8 per thread. 128 blocks = 1 wave.
// ---------------------------------------------------------------------------
__global__ __launch_bounds__(256) void k_gemm2(
    const float* __restrict__ x, float* __restrict__ out)
{
    constexpr int BK = 32;
    __shared__ float As[BK][65];     // [k][c]
    __shared__ float Bs[BK][260];    // [k][p]
    int b  = blockIdx.y;
    int p0 = blockIdx.x * 256;
    const float* Ab = g_base + (size_t)b * kC * kN;
    const float* Yb = g_buf2 + (size_t)b * kHW * kNS;
    int tid = threadIdx.x;
    int tx = tid & 31, ty = tid >> 5;
    float acc[8][8] = {};

    for (int k0 = 0; k0 < kN; k0 += BK) {
        // A tile: 64x32, coalesced over k
#pragma unroll
        for (int i = tid; i < 64 * BK; i += 256) {
            int c = i >> 5, kk = i & 31;
            int k = k0 + kk;
            As[kk][c] = (k < kN) ? Ab[(size_t)c * kN + k] : 0.f;
        }
        // B tile: T[p][m] computed on the fly; consecutive tid -> consecutive m
#pragma unroll
        for (int i = tid; i < 256 * BK; i += 256) {
            int pp = i >> 5, kk = i & 31;
            int m = k0 + kk;
            float s = 0.f;
            if (m < kN) {
                int ny, nx, wl;
                n_geom(m, ny, nx, wl);
                int p  = p0 + pp;
                int py = p >> 5, px = p & 31;
#pragma unroll
                for (int dy = -1; dy <= 1; dy++) {
                    int qy = py + dy, my = ny + dy;
                    if ((unsigned)qy >= 32u || (unsigned)my >= (unsigned)wl) continue;
#pragma unroll
                    for (int dx = -1; dx <= 1; dx++) {
                        int qx = px + dx, mxx = nx + dx;
                        if ((unsigned)qx >= 32u || (unsigned)mxx >= (unsigned)wl) continue;
                        s += Yb[(size_t)(qy * 32 + qx) * kNS + (m + dy * wl + dx)];
                    }
                }
            }
            Bs[kk][pp] = s;
        }
        __syncthreads();
#pragma unroll
        for (int k = 0; k < BK; k++) {
            float av[8], bv[8];
#pragma unroll
            for (int r = 0; r < 8; r++) av[r] = As[k][ty + r * 8];
#pragma unroll
            for (int l = 0; l < 8; l++) bv[l] = Bs[k][tx + l * 32];
#pragma unroll
            for (int r = 0; r < 8; r++)
#pragma unroll
                for (int l = 0; l < 8; l++) acc[r][l] = fmaf(av[r], bv[l], acc[r][l]);
        }
        __syncthreads();
    }

    const float* xb = x   + (size_t)b * kC * kHW;
    float*       ob = out + (size_t)b * kC * kHW;
#pragma unroll
    for (int r = 0; r < 8; r++) {
        int c = ty + r * 8;
#pragma unroll
        for (int l = 0; l < 8; l++) {
            int p = p0 + tx + l * 32;
            ob[(size_t)c * kHW + p] = fmaf(0.25f, acc[r][l], xb[(size_t)c * kHW + p]);
        }
    }
}

// ---------------------------------------------------------------------------
extern "C" void kernel_launch(void* const* d_in, const int* in_sizes, int n_in,
                              void* d_out, int out_size)
{
    (void)in_sizes; (void)n_in; (void)out_size;
    const float* x       = (const float*)d_in[0];
    const float* w_base  = (const float*)d_in[1];
    const float* b_base  = (const float*)d_in[2];
    const float* a_base  = (const float*)d_in[3];
    const float* w_match = (const float*)d_in[4];
    const float* b_match = (const float*)d_in[5];
    const float* a_match = (const float*)d_in[6];
    const float* w_asm   = (const float*)d_in[7];
    const float* b_asm   = (const float*)d_in[8];
    const float* a_asm   = (const float*)d_in[9];
    float* out = (float*)d_out;

    // projections (+ fused refm sum-of-squares)
    k_conv_main<<<(kB * kC2 * kHW + 255) / 256, 256>>>(x, w_base, b_base, a_base);
    {
        dim3 g((kN + 255) / 256, kB);
        k_conv_pyr<kC2, 0><<<g, 256>>>(x, w_match, b_match, a_match);  // -> g_refm, g_sq
        k_conv_pyr<kC,  1><<<g, 256>>>(x, w_asm,   b_asm,   a_asm);    // -> g_base
    }
    k_invn<<<(kB * kN + 255) / 256, 256>>>();
    // pixel-level correlation S
    {
        dim3 g((kN + 63) / 64, kHW / 64, kB);
        k_gemm1<<<g, 256>>>();
    }
    // fused stencil + softmax -> yn
    {
        dim3 g(kHW, kB);
        k_softmax<<<g, 256>>>();
    }
    // fused T-stencil + fold GEMM + residual
    {
        dim3 g(kHW / 256, kB);
        k_gemm2<<<g, 256>>>(x, out);
    }
}

// round 5
// speedup vs baseline: 2.1160x; 2.1160x over previous
#include <cuda_runtime.h>

// ---------------------------------------------------------------------------
// PyramidAttention (UrbanODE core), B=32, C=64, H=W=32, 5 scales, N=3278.
//
//   S[m,q]      = sum_c refm[c,m] * match[c,q]              (K=32 GEMM)
//   logit[n,p]  = 10*invnorm[n] * sum_d S[n+d, p+d]         } fused with softmax
//   yn          = softmax over n (per (b,p))                } (row lives in smem)
//   T[p,m]      = sum_d yn[m+d, p+d]                        (standalone stencil)
//   out[c,p]    = x[c,p] + 0.25 * sum_m base[c,m] * T[p,m]  (K=3278 GEMM)
//
// R5: revert R4's gemm2/stencil fusion (occupancy collapse: 128 blocks,
// serialized 288-load B phase, register pressure). Keep softmax fusion.
// ---------------------------------------------------------------------------

namespace {
constexpr int kB  = 32;
constexpr int kC  = 64;
constexpr int kC2 = 32;
constexpr int kHW = 1024;
constexpr int kN  = 3278;   // 1024+784+625+484+361
constexpr int kNS = 3280;   // padded row stride
}

// scratch (device globals: allocation-free rule)
__device__ float  g_match[(size_t)kB * kC2 * kHW];
__device__ float  g_refm [(size_t)kB * kC2 * kN];
__device__ float  g_base [(size_t)kB * kC  * kN];
__device__ float  g_sq   [(size_t)kB * kN];
__device__ float  g_invn [(size_t)kB * kN];
__device__ float  g_buf1 [(size_t)kB * kHW * kNS];  // S, later T
__device__ float  g_buf2 [(size_t)kB * kHW * kNS];  // yn

// pyramid pixel -> (level-local y, x, level width). levels are square.
__device__ __forceinline__ void n_geom(int n, int& ny, int& nx, int& wl)
{
    if (n < 1024)      { int loc = n;        ny = loc >> 5;  nx = loc & 31;     wl = 32; }
    else if (n < 1808) { int loc = n - 1024; ny = loc / 28;  nx = loc - ny*28;  wl = 28; }
    else if (n < 2433) { int loc = n - 1808; ny = loc / 25;  nx = loc - ny*25;  wl = 25; }
    else if (n < 2917) { int loc = n - 2433; ny = loc / 22;  nx = loc - ny*22;  wl = 22; }
    else               { int loc = n - 2917; ny = loc / 19;  nx = loc - ny*19;  wl = 19; }
}

// ---------------------------------------------------------------------------
// match_base = prelu(conv1x1(x, w_base)) : [B,32,1024]
// ---------------------------------------------------------------------------
__global__ __launch_bounds__(256) void k_conv_main(
    const float* __restrict__ x, const float* __restrict__ w,
    const float* __restrict__ bias, const float* __restrict__ a)
{
    int t = blockIdx.x * blockDim.x + threadIdx.x;
    if (t >= kB * kC2 * kHW) return;
    int p  = t & (kHW - 1);
    int co = (t >> 10) & 31;
    int b  = t >> 15;
    const float* xb = x + ((size_t)b * kC) * kHW + p;
    const float* wr = w + co * kC;
    float acc = bias[co];
#pragma unroll
    for (int c = 0; c < kC; c++) acc = fmaf(wr[c], xb[(size_t)c * kHW], acc);
    float al = a[0];
    g_match[t] = acc >= 0.f ? acc : al * acc;
}

// ---------------------------------------------------------------------------
// pyramid conv1x1 + prelu (nearest-resize folded into indexing).
// DST=0 -> g_refm (also writes g_sq = sum of squares), DST=1 -> g_base.
// ---------------------------------------------------------------------------
template <int COUT, int DST>
__global__ __launch_bounds__(256) void k_conv_pyr(
    const float* __restrict__ x, const float* __restrict__ w,
    const float* __restrict__ bias, const float* __restrict__ a)
{
    __shared__ float ws[COUT * kC];
    for (int i = threadIdx.x; i < COUT * kC; i += 256) ws[i] = w[i];
    __syncthreads();

    int n = blockIdx.x * 256 + threadIdx.x;
    int b = blockIdx.y;
    if (n >= kN) return;

    int ny, nx, wl;
    n_geom(n, ny, nx, wl);
    int sy = (ny * 32) / wl;
    int sx = (nx * 32) / wl;
    const float* xb = x + ((size_t)b * kC) * kHW + sy * 32 + sx;

    float acc[COUT];
#pragma unroll
    for (int co = 0; co < COUT; co++) acc[co] = bias[co];
#pragma unroll 4
    for (int c = 0; c < kC; c++) {
        float xv = xb[(size_t)c * kHW];
#pragma unroll
        for (int co = 0; co < COUT; co++) acc[co] = fmaf(ws[co * kC + c], xv, acc[co]);
    }
    float al = a[0];
    float* ob = (DST == 0 ? g_refm : g_base) + (size_t)b * COUT * kN + n;
    float sq = 0.f;
#pragma unroll
    for (int co = 0; co < COUT; co++) {
        float v = acc[co];
        v = v >= 0.f ? v : al * v;
        ob[(size_t)co * kN] = v;
        sq = fmaf(v, v, sq);
    }
    if (DST == 0) g_sq[(size_t)b * kN + n] = sq;
}

// invnorm[n] = 10 / max(sqrt(sum_{valid d} sq[n+d]), 1e-4)
__global__ __launch_bounds__(256) void k_invn()
{
    int t = blockIdx.x * blockDim.x + threadIdx.x;
    if (t >= kB * kN) return;
    int n = t % kN, b = t / kN;
    int ny, nx, wl;
    n_geom(n, ny, nx, wl);
    const float* sq = g_sq + (size_t)b * kN;
    float s = 0.f;
#pragma unroll
    for (int dy = -1; dy <= 1; dy++) {
        int my = ny + dy;
        if ((unsigned)my >= (unsigned)wl) continue;
#pragma unroll
        for (int dx = -1; dx <= 1; dx++) {
            int mx = nx + dx;
            if ((unsigned)mx >= (unsigned)wl) continue;
            s += sq[n + dy * wl + dx];
        }
    }
    float nr = fmaxf(sqrtf(s), 1e-4f);
    g_invn[t] = 10.f / nr;
}

// ---------------------------------------------------------------------------
// GEMM1: S[b][p][n] = sum_{c<32} match[b][c][p] * refm[b][c][n]
// ---------------------------------------------------------------------------
__global__ __launch_bounds__(256) void k_gemm1()
{
    __shared__ float As[32][65];  // [k][p]
    __shared__ float Bs[32][65];  // [k][n]
    int b  = blockIdx.z;
    int p0 = blockIdx.y * 64;
    int n0 = blockIdx.x * 64;
    const float* Ab = g_match + (size_t)b * kC2 * kHW;
    const float* Bb = g_refm  + (size_t)b * kC2 * kN;
    int tid = threadIdx.x;
#pragma unroll
    for (int i = tid; i < 32 * 64; i += 256) {
        int k = i >> 6, j = i & 63;
        As[k][j] = Ab[(size_t)k * kHW + p0 + j];
        int n = n0 + j;
        Bs[k][j] = (n < kN) ? Bb[(size_t)k * kN + n] : 0.f;
    }
    __syncthreads();
    int tx = tid & 15, ty = tid >> 4;
    float acc[4][4] = {};
#pragma unroll
    for (int k = 0; k < 32; k++) {
        float av[4], bv[4];
#pragma unroll
        for (int r = 0; r < 4; r++) av[r] = As[k][ty + r * 16];
#pragma unroll
        for (int l = 0; l < 4; l++) bv[l] = Bs[k][tx + l * 16];
#pragma unroll
        for (int r = 0; r < 4; r++)
#pragma unroll
            for (int l = 0; l < 4; l++) acc[r][l] = fmaf(av[r], bv[l], acc[r][l]);
    }
    float* Sb = g_buf1 + (size_t)b * kHW * kNS;
#pragma unroll
    for (int r = 0; r < 4; r++) {
        int p = p0 + ty + r * 16;
#pragma unroll
        for (int l = 0; l < 4; l++) {
            int n = n0 + tx + l * 16;
            if (n < kN) Sb[(size_t)p * kNS + n] = acc[r][l];
        }
    }
}

// ---------------------------------------------------------------------------
// FUSED: logits (9-tap diag stencil of S, scaled by invnorm) + row softmax.
// One block per (p, b); the 3278-logit row lives in smem.  buf1 -> buf2
// ---------------------------------------------------------------------------
__global__ __launch_bounds__(256) void k_softmax()
{
    __shared__ float row[kNS];
    __shared__ float red[8];
    int p = blockIdx.x, b = blockIdx.y;
    int tid = threadIdx.x;
    int lane = tid & 31, wid = tid >> 5;
    int py = p >> 5, px = p & 31;
    const float* S    = g_buf1 + (size_t)b * kHW * kNS;
    const float* invn = g_invn + (size_t)b * kN;

    float mx = -3.4e38f;
    for (int n = tid; n < kN; n += 256) {
        int ny, nx, wl;
        n_geom(n, ny, nx, wl);
        float s = 0.f;
#pragma unroll
        for (int dy = -1; dy <= 1; dy++) {
            int qy = py + dy, my = ny + dy;
            if ((unsigned)qy >= 32u || (unsigned)my >= (unsigned)wl) continue;
#pragma unroll
            for (int dx = -1; dx <= 1; dx++) {
                int qx = px + dx, mxx = nx + dx;
                if ((unsigned)qx >= 32u || (unsigned)mxx >= (unsigned)wl) continue;
                s += S[(size_t)(qy * 32 + qx) * kNS + (n + dy * wl + dx)];
            }
        }
        s *= invn[n];
        row[n] = s;
        mx = fmaxf(mx, s);
    }
#pragma unroll
    for (int o = 16; o > 0; o >>= 1) mx = fmaxf(mx, __shfl_xor_sync(0xffffffffu, mx, o));
    if (lane == 0) red[wid] = mx;
    __syncthreads();
    mx = red[0];
#pragma unroll
    for (int i = 1; i < 8; i++) mx = fmaxf(mx, red[i]);
    __syncthreads();

    float sum = 0.f;
    for (int n = tid; n < kN; n += 256) {
        float e = __expf(row[n] - mx);
        row[n] = e;
        sum += e;
    }
#pragma unroll
    for (int o = 16; o > 0; o >>= 1) sum += __shfl_xor_sync(0xffffffffu, sum, o);
    if (lane == 0) red[wid] = sum;
    __syncthreads();
    sum = red[0];
#pragma unroll
    for (int i = 1; i < 8; i++) sum += red[i];
    float inv = 1.f / sum;

    float* yn = g_buf2 + ((size_t)b * kHW + p) * kNS;
    for (int n = tid; n < kN; n += 256) yn[n] = row[n] * inv;
}

// ---------------------------------------------------------------------------
// T[b][p][m] = sum_{valid d} yn[b][p+d][m+d]      buf2 -> buf1
// High-occupancy: one thread per (n, p); coalesced over n.
// ---------------------------------------------------------------------------
__global__ __launch_bounds__(256) void k_stencilT()
{
    int n = blockIdx.x * 256 + threadIdx.x;
    if (n >= kN) return;
    int p = blockIdx.y, b = blockIdx.z;
    int ny, nx, wl;
    n_geom(n, ny, nx, wl);
    int py = p >> 5, px = p & 31;
    const float* Y = g_buf2 + (size_t)b * kHW * kNS;
    float s = 0.f;
#pragma unroll
    for (int dy = -1; dy <= 1; dy++) {
        int qy = py + dy, my = ny + dy;
        if ((unsigned)qy >= 32u || (unsigned)my >= (unsigned)wl) continue;
#pragma unroll
        for (int dx = -1; dx <= 1; dx++) {
            int qx = px + dx, mxx = nx + dx;
            if ((unsigned)qx >= 32u || (unsigned)mxx >= (unsigned)wl) continue;
            s += Y[(size_t)(qy * 32 + qx) * kNS + (n + dy * wl + dx)];
        }
    }
    g_buf1[((size_t)b * kHW + p) * kNS + n] = s;
}

// ---------------------------------------------------------------------------
// GEMM2 + epilogue: out[b][c][p] = x[b][c][p] + 0.25 * sum_m base[b][c][m]*T[b][p][m]
// Tile 64c x 128p, BK=32; 256 threads, 8x4 per thread; 256 blocks (~2/SM).
// ---------------------------------------------------------------------------
__global__ __launch_bounds__(256) void k_gemm2(
    const float* __restrict__ x, float* __restrict__ out)
{
    constexpr int BK = 32;
    __shared__ float As[BK][65];    // [k][c]
    __shared__ float Bs[BK][133];   // [k][p]
    int b  = blockIdx.y;
    int p0 = blockIdx.x * 128;
    const float* Ab = g_base + (size_t)b * kC * kN;
    const float* Tb = g_buf1 + (size_t)b * kHW * kNS;
    int tid = threadIdx.x;
    int tx = tid & 31, ty = tid >> 5;
    float acc[8][4] = {};

    for (int k0 = 0; k0 < kN; k0 += BK) {
#pragma unroll
        for (int i = tid; i < 64 * BK; i += 256) {
            int c = i >> 5, kk = i & 31;
            int k = k0 + kk;
            As[kk][c] = (k < kN) ? Ab[(size_t)c * kN + k] : 0.f;
        }
#pragma unroll
        for (int i = tid; i < 128 * BK; i += 256) {
            int pp = i >> 5, kk = i & 31;
            int k = k0 + kk;
            Bs[kk][pp] = (k < kN) ? Tb[(size_t)(p0 + pp) * kNS + k] : 0.f;
        }
        __syncthreads();
#pragma unroll
        for (int k = 0; k < BK; k++) {
            float av[8], bv[4];
#pragma unroll
            for (int r = 0; r < 8; r++) av[r] = As[k][ty + r * 8];
#pragma unroll
            for (int l = 0; l < 4; l++) bv[l] = Bs[k][tx + l * 32];
#pragma unroll
            for (int r = 0; r < 8; r++)
#pragma unroll
                for (int l = 0; l < 4; l++) acc[r][l] = fmaf(av[r], bv[l], acc[r][l]);
        }
        __syncthreads();
    }

    const float* xb = x   + (size_t)b * kC * kHW;
    float*       ob = out + (size_t)b * kC * kHW;
#pragma unroll
    for (int r = 0; r < 8; r++) {
        int c = ty + r * 8;
#pragma unroll
        for (int l = 0; l < 4; l++) {
            int p = p0 + tx + l * 32;
            ob[(size_t)c * kHW + p] = fmaf(0.25f, acc[r][l], xb[(size_t)c * kHW + p]);
        }
    }
}

// ---------------------------------------------------------------------------
extern "C" void kernel_launch(void* const* d_in, const int* in_sizes, int n_in,
                              void* d_out, int out_size)
{
    (void)in_sizes; (void)n_in; (void)out_size;
    const float* x       = (const float*)d_in[0];
    const float* w_base  = (const float*)d_in[1];
    const float* b_base  = (const float*)d_in[2];
    const float* a_base  = (const float*)d_in[3];
    const float* w_match = (const float*)d_in[4];
    const float* b_match = (const float*)d_in[5];
    const float* a_match = (const float*)d_in[6];
    const float* w_asm   = (const float*)d_in[7];
    const float* b_asm   = (const float*)d_in[8];
    const float* a_asm   = (const float*)d_in[9];
    float* out = (float*)d_out;

    // projections (+ fused refm sum-of-squares)
    k_conv_main<<<(kB * kC2 * kHW + 255) / 256, 256>>>(x, w_base, b_base, a_base);
    {
        dim3 g((kN + 255) / 256, kB);
        k_conv_pyr<kC2, 0><<<g, 256>>>(x, w_match, b_match, a_match);  // -> g_refm, g_sq
        k_conv_pyr<kC,  1><<<g, 256>>>(x, w_asm,   b_asm,   a_asm);    // -> g_base
    }
    k_invn<<<(kB * kN + 255) / 256, 256>>>();
    // pixel-level correlation S
    {
        dim3 g((kN + 63) / 64, kHW / 64, kB);
        k_gemm1<<<g, 256>>>();
    }
    // fused stencil + softmax -> yn
    {
        dim3 g(kHW, kB);
        k_softmax<<<g, 256>>>();
    }
    // T stencil (high occupancy)
    {
        dim3 g((kN + 255) / 256, kHW, kB);
        k_stencilT<<<g, 256>>>();
    }
    // fold GEMM + residual
    {
        dim3 g(kHW / 128, kB);
        k_gemm2<<<g, 256>>>(x, out);
    }
}

// round 6
// speedup vs baseline: 2.3192x; 1.0960x over previous
#include <cuda_runtime.h>
#include <cuda_fp16.h>

// ---------------------------------------------------------------------------
// PyramidAttention (UrbanODE core), B=32, C=64, H=W=32, 5 scales, N=3278.
//
//   S[m,q]      = sum_c refm[c,m] * match[c,q]              (K=32 GEMM, fp32)
//   logit[n,p]  = 10*invnorm[n] * sum_d S[n+d, p+d]         } fused with softmax
//   yn          = softmax over n (per (b,p))                } -> fp16
//   T[p,m]      = sum_d yn[m+d, p+d]                        (fp16 stencil)
//   out[c,p]    = x[c,p] + 0.25 * sum_m base[c,m] * T[p,m]  (K=3278 GEMM, fp32 acc)
//
// R6: fp16 yn/T (halves stencil+gemm2 traffic; safe: values in [0,1], fold
// term only ~26% of output); per-n validity/width table kills the IDIV-heavy
// n_geom in the two hot stencil loops (107M evals each).
// ---------------------------------------------------------------------------

namespace {
constexpr int kB  = 32;
constexpr int kC  = 64;
constexpr int kC2 = 32;
constexpr int kHW = 1024;
constexpr int kN  = 3278;   // 1024+784+625+484+361
constexpr int kNS = 3280;   // padded row stride
}

// scratch (device globals: allocation-free rule)
__device__ float    g_match[(size_t)kB * kC2 * kHW];
__device__ float    g_refm [(size_t)kB * kC2 * kN];
__device__ float    g_base [(size_t)kB * kC  * kN];
__device__ float    g_sq   [(size_t)kB * kN];
__device__ float    g_invn [(size_t)kB * kN];
__device__ unsigned g_tab  [kN];                     // bits[0:9] pyr validity, bits[9:16] wl
__device__ float    g_S    [(size_t)kB * kHW * kNS]; // fp32 correlation
__device__ __half   g_yn   [(size_t)kB * kHW * kNS]; // fp16 softmax output
__device__ __half   g_T    [(size_t)kB * kHW * kNS]; // fp16 folded weights

// pyramid pixel -> (level-local y, x, level width). levels are square.
__device__ __forceinline__ void n_geom(int n, int& ny, int& nx, int& wl)
{
    if (n < 1024)      { int loc = n;        ny = loc >> 5;  nx = loc & 31;     wl = 32; }
    else if (n < 1808) { int loc = n - 1024; ny = loc / 28;  nx = loc - ny*28;  wl = 28; }
    else if (n < 2433) { int loc = n - 1808; ny = loc / 25;  nx = loc - ny*25;  wl = 25; }
    else if (n < 2917) { int loc = n - 2433; ny = loc / 22;  nx = loc - ny*22;  wl = 22; }
    else               { int loc = n - 2917; ny = loc / 19;  nx = loc - ny*19;  wl = 19; }
}

// ---------------------------------------------------------------------------
// match_base = prelu(conv1x1(x, w_base)) : [B,32,1024]
// ---------------------------------------------------------------------------
__global__ __launch_bounds__(256) void k_conv_main(
    const float* __restrict__ x, const float* __restrict__ w,
    const float* __restrict__ bias, const float* __restrict__ a)
{
    int t = blockIdx.x * blockDim.x + threadIdx.x;
    if (t >= kB * kC2 * kHW) return;
    int p  = t & (kHW - 1);
    int co = (t >> 10) & 31;
    int b  = t >> 15;
    const float* xb = x + ((size_t)b * kC) * kHW + p;
    const float* wr = w + co * kC;
    float acc = bias[co];
#pragma unroll
    for (int c = 0; c < kC; c++) acc = fmaf(wr[c], xb[(size_t)c * kHW], acc);
    float al = a[0];
    g_match[t] = acc >= 0.f ? acc : al * acc;
}

// ---------------------------------------------------------------------------
// pyramid conv1x1 + prelu (nearest-resize folded into indexing).
// DST=0 -> g_refm (also writes g_sq), DST=1 -> g_base.
// ---------------------------------------------------------------------------
template <int COUT, int DST>
__global__ __launch_bounds__(256) void k_conv_pyr(
    const float* __restrict__ x, const float* __restrict__ w,
    const float* __restrict__ bias, const float* __restrict__ a)
{
    __shared__ float ws[COUT * kC];
    for (int i = threadIdx.x; i < COUT * kC; i += 256) ws[i] = w[i];
    __syncthreads();

    int n = blockIdx.x * 256 + threadIdx.x;
    int b = blockIdx.y;
    if (n >= kN) return;

    int ny, nx, wl;
    n_geom(n, ny, nx, wl);
    int sy = (ny * 32) / wl;
    int sx = (nx * 32) / wl;
    const float* xb = x + ((size_t)b * kC) * kHW + sy * 32 + sx;

    float acc[COUT];
#pragma unroll
    for (int co = 0; co < COUT; co++) acc[co] = bias[co];
#pragma unroll 4
    for (int c = 0; c < kC; c++) {
        float xv = xb[(size_t)c * kHW];
#pragma unroll
        for (int co = 0; co < COUT; co++) acc[co] = fmaf(ws[co * kC + c], xv, acc[co]);
    }
    float al = a[0];
    float* ob = (DST == 0 ? g_refm : g_base) + (size_t)b * COUT * kN + n;
    float sq = 0.f;
#pragma unroll
    for (int co = 0; co < COUT; co++) {
        float v = acc[co];
        v = v >= 0.f ? v : al * v;
        ob[(size_t)co * kN] = v;
        sq = fmaf(v, v, sq);
    }
    if (DST == 0) g_sq[(size_t)b * kN + n] = sq;
}

// invnorm[n] = 10 / max(sqrt(sum_{valid d} sq[n+d]), 1e-4); b==0 also builds g_tab
__global__ __launch_bounds__(256) void k_invn()
{
    int t = blockIdx.x * blockDim.x + threadIdx.x;
    if (t >= kB * kN) return;
    int n = t % kN, b = t / kN;
    int ny, nx, wl;
    n_geom(n, ny, nx, wl);
    const float* sq = g_sq + (size_t)b * kN;
    float s = 0.f;
    unsigned m = 0;
    int i = 0;
#pragma unroll
    for (int dy = -1; dy <= 1; dy++) {
#pragma unroll
        for (int dx = -1; dx <= 1; dx++, i++) {
            int my = ny + dy, mx = nx + dx;
            if ((unsigned)my < (unsigned)wl && (unsigned)mx < (unsigned)wl) {
                s += sq[n + dy * wl + dx];
                m |= 1u << i;
            }
        }
    }
    float nr = fmaxf(sqrtf(s), 1e-4f);
    g_invn[t] = 10.f / nr;
    if (b == 0) g_tab[n] = m | ((unsigned)wl << 9);
}

// ---------------------------------------------------------------------------
// GEMM1: S[b][p][n] = sum_{c<32} match[b][c][p] * refm[b][c][n]
// ---------------------------------------------------------------------------
__global__ __launch_bounds__(256) void k_gemm1()
{
    __shared__ float As[32][65];  // [k][p]
    __shared__ float Bs[32][65];  // [k][n]
    int b  = blockIdx.z;
    int p0 = blockIdx.y * 64;
    int n0 = blockIdx.x * 64;
    const float* Ab = g_match + (size_t)b * kC2 * kHW;
    const float* Bb = g_refm  + (size_t)b * kC2 * kN;
    int tid = threadIdx.x;
#pragma unroll
    for (int i = tid; i < 32 * 64; i += 256) {
        int k = i >> 6, j = i & 63;
        As[k][j] = Ab[(size_t)k * kHW + p0 + j];
        int n = n0 + j;
        Bs[k][j] = (n < kN) ? Bb[(size_t)k * kN + n] : 0.f;
    }
    __syncthreads();
    int tx = tid & 15, ty = tid >> 4;
    float acc[4][4] = {};
#pragma unroll
    for (int k = 0; k < 32; k++) {
        float av[4], bv[4];
#pragma unroll
        for (int r = 0; r < 4; r++) av[r] = As[k][ty + r * 16];
#pragma unroll
        for (int l = 0; l < 4; l++) bv[l] = Bs[k][tx + l * 16];
#pragma unroll
        for (int r = 0; r < 4; r++)
#pragma unroll
            for (int l = 0; l < 4; l++) acc[r][l] = fmaf(av[r], bv[l], acc[r][l]);
    }
    float* Sb = g_S + (size_t)b * kHW * kNS;
#pragma unroll
    for (int r = 0; r < 4; r++) {
        int p = p0 + ty + r * 16;
#pragma unroll
        for (int l = 0; l < 4; l++) {
            int n = n0 + tx + l * 16;
            if (n < kN) Sb[(size_t)p * kNS + n] = acc[r][l];
        }
    }
}

// block-uniform p-side mask + 9 query-row indices
__device__ __forceinline__ unsigned p_taps(int p, int* qrow)
{
    int py = p >> 5, px = p & 31;
    unsigned pm = 0;
    int i = 0;
#pragma unroll
    for (int dy = -1; dy <= 1; dy++) {
#pragma unroll
        for (int dx = -1; dx <= 1; dx++, i++) {
            int qy = py + dy, qx = px + dx;
            qrow[i] = qy * 32 + qx;
            if ((unsigned)qy < 32u && (unsigned)qx < 32u) pm |= 1u << i;
        }
    }
    return pm;
}

// ---------------------------------------------------------------------------
// FUSED: logits (9-tap diag stencil of S, scaled by invnorm) + row softmax.
// One block per (p, b); the 3278-logit row lives in smem.  S -> yn (fp16)
// ---------------------------------------------------------------------------
__global__ __launch_bounds__(256) void k_softmax()
{
    __shared__ float row[kNS];
    __shared__ float red[8];
    int p = blockIdx.x, b = blockIdx.y;
    int tid = threadIdx.x;
    int lane = tid & 31, wid = tid >> 5;
    const float* S    = g_S    + (size_t)b * kHW * kNS;
    const float* invn = g_invn + (size_t)b * kN;

    int qrow[9];
    unsigned pm = p_taps(p, qrow);

    float mx = -3.4e38f;
    for (int n = tid; n < kN; n += 256) {
        unsigned tb = g_tab[n];
        int wl = (int)(tb >> 9);
        unsigned m = tb & pm;
        int off[9] = {-wl - 1, -wl, -wl + 1, -1, 0, 1, wl - 1, wl, wl + 1};
        float s = 0.f;
#pragma unroll
        for (int i = 0; i < 9; i++)
            if ((m >> i) & 1u) s += S[(size_t)qrow[i] * kNS + n + off[i]];
        s *= invn[n];
        row[n] = s;
        mx = fmaxf(mx, s);
    }
#pragma unroll
    for (int o = 16; o > 0; o >>= 1) mx = fmaxf(mx, __shfl_xor_sync(0xffffffffu, mx, o));
    if (lane == 0) red[wid] = mx;
    __syncthreads();
    mx = red[0];
#pragma unroll
    for (int i = 1; i < 8; i++) mx = fmaxf(mx, red[i]);
    __syncthreads();

    float sum = 0.f;
    for (int n = tid; n < kN; n += 256) {
        float e = __expf(row[n] - mx);
        row[n] = e;
        sum += e;
    }
#pragma unroll
    for (int o = 16; o > 0; o >>= 1) sum += __shfl_xor_sync(0xffffffffu, sum, o);
    if (lane == 0) red[wid] = sum;
    __syncthreads();
    sum = red[0];
#pragma unroll
    for (int i = 1; i < 8; i++) sum += red[i];
    float inv = 1.f / sum;

    __half* yn = g_yn + ((size_t)b * kHW + p) * kNS;
    for (int n = tid; n < kN; n += 256) yn[n] = __float2half(row[n] * inv);
}

// ---------------------------------------------------------------------------
// T[b][p][m] = sum_{valid d} yn[b][p+d][m+d]      (fp16 in/out)
// ---------------------------------------------------------------------------
__global__ __launch_bounds__(256) void k_stencilT()
{
    int n = blockIdx.x * 256 + threadIdx.x;
    if (n >= kN) return;
    int p = blockIdx.y, b = blockIdx.z;
    const __half* Y = g_yn + (size_t)b * kHW * kNS;

    int qrow[9];
    unsigned pm = p_taps(p, qrow);
    unsigned tb = g_tab[n];
    int wl = (int)(tb >> 9);
    unsigned m = tb & pm;
    int off[9] = {-wl - 1, -wl, -wl + 1, -1, 0, 1, wl - 1, wl, wl + 1};
    float s = 0.f;
#pragma unroll
    for (int i = 0; i < 9; i++)
        if ((m >> i) & 1u) s += __half2float(Y[(size_t)qrow[i] * kNS + n + off[i]]);
    g_T[((size_t)b * kHW + p) * kNS + n] = __float2half(s);
}

// ---------------------------------------------------------------------------
// GEMM2 + epilogue: out[b][c][p] = x[b][c][p] + 0.25 * sum_m base[b][c][m]*T[b][p][m]
// Tile 64c x 128p, BK=32; 256 threads, 8x4 per thread; 256 blocks (~2/SM).
// ---------------------------------------------------------------------------
__global__ __launch_bounds__(256) void k_gemm2(
    const float* __restrict__ x, float* __restrict__ out)
{
    constexpr int BK = 32;
    __shared__ float As[BK][65];    // [k][c]
    __shared__ float Bs[BK][133];   // [k][p]
    int b  = blockIdx.y;
    int p0 = blockIdx.x * 128;
    const float*  Ab = g_base + (size_t)b * kC * kN;
    const __half* Tb = g_T    + (size_t)b * kHW * kNS;
    int tid = threadIdx.x;
    int tx = tid & 31, ty = tid >> 5;
    float acc[8][4] = {};

    for (int k0 = 0; k0 < kN; k0 += BK) {
#pragma unroll
        for (int i = tid; i < 64 * BK; i += 256) {
            int c = i >> 5, kk = i & 31;
            int k = k0 + kk;
            As[kk][c] = (k < kN) ? Ab[(size_t)c * kN + k] : 0.f;
        }
#pragma unroll
        for (int i = tid; i < 128 * BK; i += 256) {
            int pp = i >> 5, kk = i & 31;
            int k = k0 + kk;
            Bs[kk][pp] = (k < kN) ? __half2float(Tb[(size_t)(p0 + pp) * kNS + k]) : 0.f;
        }
        __syncthreads();
#pragma unroll
        for (int k = 0; k < BK; k++) {
            float av[8], bv[4];
#pragma unroll
            for (int r = 0; r < 8; r++) av[r] = As[k][ty + r * 8];
#pragma unroll
            for (int l = 0; l < 4; l++) bv[l] = Bs[k][tx + l * 32];
#pragma unroll
            for (int r = 0; r < 8; r++)
#pragma unroll
                for (int l = 0; l < 4; l++) acc[r][l] = fmaf(av[r], bv[l], acc[r][l]);
        }
        __syncthreads();
    }

    const float* xb = x   + (size_t)b * kC * kHW;
    float*       ob = out + (size_t)b * kC * kHW;
#pragma unroll
    for (int r = 0; r < 8; r++) {
        int c = ty + r * 8;
#pragma unroll
        for (int l = 0; l < 4; l++) {
            int p = p0 + tx + l * 32;
            ob[(size_t)c * kHW + p] = fmaf(0.25f, acc[r][l], xb[(size_t)c * kHW + p]);
        }
    }
}

// ---------------------------------------------------------------------------
extern "C" void kernel_launch(void* const* d_in, const int* in_sizes, int n_in,
                              void* d_out, int out_size)
{
    (void)in_sizes; (void)n_in; (void)out_size;
    const float* x       = (const float*)d_in[0];
    const float* w_base  = (const float*)d_in[1];
    const float* b_base  = (const float*)d_in[2];
    const float* a_base  = (const float*)d_in[3];
    const float* w_match = (const float*)d_in[4];
    const float* b_match = (const float*)d_in[5];
    const float* a_match = (const float*)d_in[6];
    const float* w_asm   = (const float*)d_in[7];
    const float* b_asm   = (const float*)d_in[8];
    const float* a_asm   = (const float*)d_in[9];
    float* out = (float*)d_out;

    // launch order puts k_gemm1 in the profiled (4th) slot
    k_conv_main<<<(kB * kC2 * kHW + 255) / 256, 256>>>(x, w_base, b_base, a_base);
    {
        dim3 g((kN + 255) / 256, kB);
        k_conv_pyr<kC2, 0><<<g, 256>>>(x, w_match, b_match, a_match);  // -> g_refm, g_sq
        k_conv_pyr<kC,  1><<<g, 256>>>(x, w_asm,   b_asm,   a_asm);    // -> g_base
    }
    {
        dim3 g((kN + 63) / 64, kHW / 64, kB);
        k_gemm1<<<g, 256>>>();                                          // 4th launch
    }
    k_invn<<<(kB * kN + 255) / 256, 256>>>();                           // also builds g_tab
    {
        dim3 g(kHW, kB);
        k_softmax<<<g, 256>>>();
    }
    {
        dim3 g((kN + 255) / 256, kHW, kB);
        k_stencilT<<<g, 256>>>();
    }
    {
        dim3 g(kHW / 128, kB);
        k_gemm2<<<g, 256>>>(x, out);
    }
}

// round 7
// speedup vs baseline: 2.8518x; 1.2297x over previous
#include <cuda_runtime.h>
#include <cuda_fp16.h>

// ---------------------------------------------------------------------------
// PyramidAttention (UrbanODE core), B=32, C=64, H=W=32, 5 scales, N=3278.
//
//   S[m,q]      = sum_c refm[c,m] * match[c,q]              (K=32 GEMM, fp32)
//   logit[n,p]  = 10*invnorm[n] * sum_d S[n+d, p+d]         } fused with softmax
//   yn          = softmax over n (per (b,p))                } -> fp16
//   T[p,m]      = sum_d yn[m+d, p+d]                        (fp16 stencil)
//   out[c,p]    = x[c,p] + 0.25 * sum_m base[c,m] * T[p,m]  (fp16 HMMA, fp32 acc)
//
// R7: gemm2 on tensor cores (mma.sync m16n8k16, fp32 accum) with fp16 base;
// gemm1 retiled to 128x128 / 8x8-per-thread (was L1tex-bound at 91.5%).
// ---------------------------------------------------------------------------

namespace {
constexpr int kB  = 32;
constexpr int kC  = 64;
constexpr int kC2 = 32;
constexpr int kHW = 1024;
constexpr int kN  = 3278;   // 1024+784+625+484+361
constexpr int kNS = 3280;   // padded row stride
}

// scratch (device globals: allocation-free rule)
__device__ float    g_match [(size_t)kB * kC2 * kHW];
__device__ float    g_refm  [(size_t)kB * kC2 * kN];
__device__ __half   g_base16[(size_t)kB * kC  * kN];
__device__ float    g_sq    [(size_t)kB * kN];
__device__ float    g_invn  [(size_t)kB * kN];
__device__ unsigned g_tab   [kN];                     // bits[0:9] pyr validity, bits[9:16] wl
__device__ float    g_S     [(size_t)kB * kHW * kNS]; // fp32 correlation
__device__ __half   g_yn    [(size_t)kB * kHW * kNS]; // fp16 softmax output
__device__ __half   g_T     [(size_t)kB * kHW * kNS]; // fp16 folded weights

// pyramid pixel -> (level-local y, x, level width). levels are square.
__device__ __forceinline__ void n_geom(int n, int& ny, int& nx, int& wl)
{
    if (n < 1024)      { int loc = n;        ny = loc >> 5;  nx = loc & 31;     wl = 32; }
    else if (n < 1808) { int loc = n - 1024; ny = loc / 28;  nx = loc - ny*28;  wl = 28; }
    else if (n < 2433) { int loc = n - 1808; ny = loc / 25;  nx = loc - ny*25;  wl = 25; }
    else if (n < 2917) { int loc = n - 2433; ny = loc / 22;  nx = loc - ny*22;  wl = 22; }
    else               { int loc = n - 2917; ny = loc / 19;  nx = loc - ny*19;  wl = 19; }
}

// ---------------------------------------------------------------------------
// match_base = prelu(conv1x1(x, w_base)) : [B,32,1024]
// ---------------------------------------------------------------------------
__global__ __launch_bounds__(256) void k_conv_main(
    const float* __restrict__ x, const float* __restrict__ w,
    const float* __restrict__ bias, const float* __restrict__ a)
{
    int t = blockIdx.x * blockDim.x + threadIdx.x;
    if (t >= kB * kC2 * kHW) return;
    int p  = t & (kHW - 1);
    int co = (t >> 10) & 31;
    int b  = t >> 15;
    const float* xb = x + ((size_t)b * kC) * kHW + p;
    const float* wr = w + co * kC;
    float acc = bias[co];
#pragma unroll
    for (int c = 0; c < kC; c++) acc = fmaf(wr[c], xb[(size_t)c * kHW], acc);
    float al = a[0];
    g_match[t] = acc >= 0.f ? acc : al * acc;
}

// ---------------------------------------------------------------------------
// pyramid conv1x1 + prelu (nearest-resize folded into indexing).
// DST=0 -> g_refm fp32 (also writes g_sq), DST=1 -> g_base16 fp16.
// ---------------------------------------------------------------------------
template <int COUT, int DST>
__global__ __launch_bounds__(256) void k_conv_pyr(
    const float* __restrict__ x, const float* __restrict__ w,
    const float* __restrict__ bias, const float* __restrict__ a)
{
    __shared__ float ws[COUT * kC];
    for (int i = threadIdx.x; i < COUT * kC; i += 256) ws[i] = w[i];
    __syncthreads();

    int n = blockIdx.x * 256 + threadIdx.x;
    int b = blockIdx.y;
    if (n >= kN) return;

    int ny, nx, wl;
    n_geom(n, ny, nx, wl);
    int sy = (ny * 32) / wl;
    int sx = (nx * 32) / wl;
    const float* xb = x + ((size_t)b * kC) * kHW + sy * 32 + sx;

    float acc[COUT];
#pragma unroll
    for (int co = 0; co < COUT; co++) acc[co] = bias[co];
#pragma unroll 4
    for (int c = 0; c < kC; c++) {
        float xv = xb[(size_t)c * kHW];
#pragma unroll
        for (int co = 0; co < COUT; co++) acc[co] = fmaf(ws[co * kC + c], xv, acc[co]);
    }
    float al = a[0];
    if (DST == 0) {
        float* ob = g_refm + (size_t)b * COUT * kN + n;
        float sq = 0.f;
#pragma unroll
        for (int co = 0; co < COUT; co++) {
            float v = acc[co];
            v = v >= 0.f ? v : al * v;
            ob[(size_t)co * kN] = v;
            sq = fmaf(v, v, sq);
        }
        g_sq[(size_t)b * kN + n] = sq;
    } else {
        __half* ob = g_base16 + (size_t)b * COUT * kN + n;
#pragma unroll
        for (int co = 0; co < COUT; co++) {
            float v = acc[co];
            v = v >= 0.f ? v : al * v;
            ob[(size_t)co * kN] = __float2half(v);
        }
    }
}

// invnorm[n] = 10 / max(sqrt(sum_{valid d} sq[n+d]), 1e-4); b==0 also builds g_tab
__global__ __launch_bounds__(256) void k_invn()
{
    int t = blockIdx.x * blockDim.x + threadIdx.x;
    if (t >= kB * kN) return;
    int n = t % kN, b = t / kN;
    int ny, nx, wl;
    n_geom(n, ny, nx, wl);
    const float* sq = g_sq + (size_t)b * kN;
    float s = 0.f;
    unsigned m = 0;
    int i = 0;
#pragma unroll
    for (int dy = -1; dy <= 1; dy++) {
#pragma unroll
        for (int dx = -1; dx <= 1; dx++, i++) {
            int my = ny + dy, mx = nx + dx;
            if ((unsigned)my < (unsigned)wl && (unsigned)mx < (unsigned)wl) {
                s += sq[n + dy * wl + dx];
                m |= 1u << i;
            }
        }
    }
    float nr = fmaxf(sqrtf(s), 1e-4f);
    g_invn[t] = 10.f / nr;
    if (b == 0) g_tab[n] = m | ((unsigned)wl << 9);
}

// ---------------------------------------------------------------------------
// GEMM1: S[b][p][n] = sum_{c<32} match[b][c][p] * refm[b][c][n]
// 128x128 tile, 8x8 per thread -> FMA-bound (64 FMA per 64 smem bytes).
// ---------------------------------------------------------------------------
__global__ __launch_bounds__(256) void k_gemm1()
{
    __shared__ float As[32][132];  // [k][p]
    __shared__ float Bs[32][132];  // [k][n]
    int b  = blockIdx.z;
    int p0 = blockIdx.y * 128;
    int n0 = blockIdx.x * 128;
    const float* Ab = g_match + (size_t)b * kC2 * kHW;
    const float* Bb = g_refm  + (size_t)b * kC2 * kN;
    int tid = threadIdx.x;
#pragma unroll
    for (int i = tid; i < 32 * 128; i += 256) {
        int k = i >> 7, j = i & 127;
        As[k][j] = Ab[(size_t)k * kHW + p0 + j];
        int n = n0 + j;
        Bs[k][j] = (n < kN) ? Bb[(size_t)k * kN + n] : 0.f;
    }
    __syncthreads();
    int tx = tid & 15, ty = tid >> 4;
    float acc[8][8] = {};
#pragma unroll
    for (int k = 0; k < 32; k++) {
        float av[8], bv[8];
#pragma unroll
        for (int r = 0; r < 8; r++) av[r] = As[k][ty + r * 16];
#pragma unroll
        for (int l = 0; l < 8; l++) bv[l] = Bs[k][tx + l * 16];
#pragma unroll
        for (int r = 0; r < 8; r++)
#pragma unroll
            for (int l = 0; l < 8; l++) acc[r][l] = fmaf(av[r], bv[l], acc[r][l]);
    }
    float* Sb = g_S + (size_t)b * kHW * kNS;
#pragma unroll
    for (int r = 0; r < 8; r++) {
        int p = p0 + ty + r * 16;
#pragma unroll
        for (int l = 0; l < 8; l++) {
            int n = n0 + tx + l * 16;
            if (n < kN) Sb[(size_t)p * kNS + n] = acc[r][l];
        }
    }
}

// block-uniform p-side mask + 9 query-row indices
__device__ __forceinline__ unsigned p_taps(int p, int* qrow)
{
    int py = p >> 5, px = p & 31;
    unsigned pm = 0;
    int i = 0;
#pragma unroll
    for (int dy = -1; dy <= 1; dy++) {
#pragma unroll
        for (int dx = -1; dx <= 1; dx++, i++) {
            int qy = py + dy, qx = px + dx;
            qrow[i] = qy * 32 + qx;
            if ((unsigned)qy < 32u && (unsigned)qx < 32u) pm |= 1u << i;
        }
    }
    return pm;
}

// ---------------------------------------------------------------------------
// FUSED: logits (9-tap diag stencil of S, scaled by invnorm) + row softmax.
// One block per (p, b); the 3278-logit row lives in smem.  S -> yn (fp16)
// ---------------------------------------------------------------------------
__global__ __launch_bounds__(256) void k_softmax()
{
    __shared__ float row[kNS];
    __shared__ float red[8];
    int p = blockIdx.x, b = blockIdx.y;
    int tid = threadIdx.x;
    int lane = tid & 31, wid = tid >> 5;
    const float* S    = g_S    + (size_t)b * kHW * kNS;
    const float* invn = g_invn + (size_t)b * kN;

    int qrow[9];
    unsigned pm = p_taps(p, qrow);

    float mx = -3.4e38f;
    for (int n = tid; n < kN; n += 256) {
        unsigned tb = g_tab[n];
        int wl = (int)(tb >> 9);
        unsigned m = tb & pm;
        int off[9] = {-wl - 1, -wl, -wl + 1, -1, 0, 1, wl - 1, wl, wl + 1};
        float s = 0.f;
#pragma unroll
        for (int i = 0; i < 9; i++)
            if ((m >> i) & 1u) s += S[(size_t)qrow[i] * kNS + n + off[i]];
        s *= invn[n];
        row[n] = s;
        mx = fmaxf(mx, s);
    }
#pragma unroll
    for (int o = 16; o > 0; o >>= 1) mx = fmaxf(mx, __shfl_xor_sync(0xffffffffu, mx, o));
    if (lane == 0) red[wid] = mx;
    __syncthreads();
    mx = red[0];
#pragma unroll
    for (int i = 1; i < 8; i++) mx = fmaxf(mx, red[i]);
    __syncthreads();

    float sum = 0.f;
    for (int n = tid; n < kN; n += 256) {
        float e = __expf(row[n] - mx);
        row[n] = e;
        sum += e;
    }
#pragma unroll
    for (int o = 16; o > 0; o >>= 1) sum += __shfl_xor_sync(0xffffffffu, sum, o);
    if (lane == 0) red[wid] = sum;
    __syncthreads();
    sum = red[0];
#pragma unroll
    for (int i = 1; i < 8; i++) sum += red[i];
    float inv = 1.f / sum;

    __half* yn = g_yn + ((size_t)b * kHW + p) * kNS;
    for (int n = tid; n < kN; n += 256) yn[n] = __float2half(row[n] * inv);
}

// ---------------------------------------------------------------------------
// T[b][p][m] = sum_{valid d} yn[b][p+d][m+d]      (fp16 in/out)
// ---------------------------------------------------------------------------
__global__ __launch_bounds__(256) void k_stencilT()
{
    int n = blockIdx.x * 256 + threadIdx.x;
    if (n >= kN) return;
    int p = blockIdx.y, b = blockIdx.z;
    const __half* Y = g_yn + (size_t)b * kHW * kNS;

    int qrow[9];
    unsigned pm = p_taps(p, qrow);
    unsigned tb = g_tab[n];
    int wl = (int)(tb >> 9);
    unsigned m = tb & pm;
    int off[9] = {-wl - 1, -wl, -wl + 1, -1, 0, 1, wl - 1, wl, wl + 1};
    float s = 0.f;
#pragma unroll
    for (int i = 0; i < 9; i++)
        if ((m >> i) & 1u) s += __half2float(Y[(size_t)qrow[i] * kNS + n + off[i]]);
    g_T[((size_t)b * kHW + p) * kNS + n] = __float2half(s);
}

// ---------------------------------------------------------------------------
// GEMM2 on tensor cores: out[b][c][p] = x[b][c][p] + 0.25*sum_m base*T
// Block tile 64c x 128p, BK=64. 8 warps in 2(c) x 4(p); each warp 32x32 via
// m16n8k16 HMMA (fp16 in, fp32 acc). Fragments via direct half2 LDS.
// ---------------------------------------------------------------------------
__global__ __launch_bounds__(256) void k_gemm2(
    const float* __restrict__ x, float* __restrict__ out)
{
    constexpr int BK = 64;
    constexpr int SA = 72;                 // half stride -> conflict-free frags
    __shared__ __half As[64 * SA];         // [c][k]
    __shared__ __half Bs[128 * SA];        // [p][k]
    int b  = blockIdx.y;
    int p0 = blockIdx.x * 128;
    const __half* Ab = g_base16 + (size_t)b * kC * kN;
    const __half* Tb = g_T      + (size_t)b * kHW * kNS;
    int tid  = threadIdx.x;
    int lane = tid & 31, warp = tid >> 5;
    int wc = (warp & 1) * 32;              // c offset of warp tile
    int wp = (warp >> 1) * 32;             // p offset of warp tile
    int gid = lane >> 2, tig = lane & 3;
    float acc[2][4][4] = {};

    for (int k0 = 0; k0 < kN; k0 += BK) {
        // A tile: 64c x 64k  (2048 half2)
#pragma unroll
        for (int j = 0; j < 8; j++) {
            int idx = tid + j * 256;
            int c = idx >> 5, kk = (idx & 31) * 2;
            int k = k0 + kk;
            unsigned v = 0;
            if (k < kN) v = *(const unsigned*)(Ab + (size_t)c * kN + k);
            *(unsigned*)(&As[c * SA + kk]) = v;
        }
        // B tile: 128p x 64k (4096 half2)
#pragma unroll
        for (int j = 0; j < 16; j++) {
            int idx = tid + j * 256;
            int pp = idx >> 5, kk = (idx & 31) * 2;
            int k = k0 + kk;
            unsigned v = 0;
            if (k < kN) v = *(const unsigned*)(Tb + (size_t)(p0 + pp) * kNS + k);
            *(unsigned*)(&Bs[pp * SA + kk]) = v;
        }
        __syncthreads();
#pragma unroll
        for (int ks = 0; ks < 4; ks++) {
            int kb = ks * 16;
            unsigned a[2][4], bf[4][2];
#pragma unroll
            for (int mt = 0; mt < 2; mt++) {
                const __half* ap = &As[(wc + mt * 16 + gid) * SA + kb + tig * 2];
                a[mt][0] = *(const unsigned*)(ap);
                a[mt][1] = *(const unsigned*)(ap + 8 * SA);
                a[mt][2] = *(const unsigned*)(ap + 8);
                a[mt][3] = *(const unsigned*)(ap + 8 * SA + 8);
            }
#pragma unroll
            for (int nt = 0; nt < 4; nt++) {
                const __half* bp = &Bs[(wp + nt * 8 + gid) * SA + kb + tig * 2];
                bf[nt][0] = *(const unsigned*)(bp);
                bf[nt][1] = *(const unsigned*)(bp + 8);
            }
#pragma unroll
            for (int mt = 0; mt < 2; mt++)
#pragma unroll
                for (int nt = 0; nt < 4; nt++) {
                    asm volatile(
                        "mma.sync.aligned.m16n8k16.row.col.f32.f16.f16.f32 "
                        "{%0,%1,%2,%3}, {%4,%5,%6,%7}, {%8,%9}, {%0,%1,%2,%3};"
                        : "+f"(acc[mt][nt][0]), "+f"(acc[mt][nt][1]),
                          "+f"(acc[mt][nt][2]), "+f"(acc[mt][nt][3])
                        : "r"(a[mt][0]), "r"(a[mt][1]), "r"(a[mt][2]), "r"(a[mt][3]),
                          "r"(bf[nt][0]), "r"(bf[nt][1]));
                }
        }
        __syncthreads();
    }

    const float* xb = x   + (size_t)b * kC * kHW;
    float*       ob = out + (size_t)b * kC * kHW;
#pragma unroll
    for (int mt = 0; mt < 2; mt++) {
        int c = wc + mt * 16 + gid;
#pragma unroll
        for (int nt = 0; nt < 4; nt++) {
            int pc = p0 + wp + nt * 8 + tig * 2;
            ob[(size_t)c * kHW + pc]           = fmaf(0.25f, acc[mt][nt][0], xb[(size_t)c * kHW + pc]);
            ob[(size_t)c * kHW + pc + 1]       = fmaf(0.25f, acc[mt][nt][1], xb[(size_t)c * kHW + pc + 1]);
            ob[(size_t)(c + 8) * kHW + pc]     = fmaf(0.25f, acc[mt][nt][2], xb[(size_t)(c + 8) * kHW + pc]);
            ob[(size_t)(c + 8) * kHW + pc + 1] = fmaf(0.25f, acc[mt][nt][3], xb[(size_t)(c + 8) * kHW + pc + 1]);
        }
    }
}

// ---------------------------------------------------------------------------
extern "C" void kernel_launch(void* const* d_in, const int* in_sizes, int n_in,
                              void* d_out, int out_size)
{
    (void)in_sizes; (void)n_in; (void)out_size;
    const float* x       = (const float*)d_in[0];
    const float* w_base  = (const float*)d_in[1];
    const float* b_base  = (const float*)d_in[2];
    const float* a_base  = (const float*)d_in[3];
    const float* w_match = (const float*)d_in[4];
    const float* b_match = (const float*)d_in[5];
    const float* a_match = (const float*)d_in[6];
    const float* w_asm   = (const float*)d_in[7];
    const float* b_asm   = (const float*)d_in[8];
    const float* a_asm   = (const float*)d_in[9];
    float* out = (float*)d_out;

    k_conv_main<<<(kB * kC2 * kHW + 255) / 256, 256>>>(x, w_base, b_base, a_base);
    {
        dim3 g((kN + 255) / 256, kB);
        k_conv_pyr<kC2, 0><<<g, 256>>>(x, w_match, b_match, a_match);  // -> g_refm, g_sq
        k_conv_pyr<kC,  1><<<g, 256>>>(x, w_asm,   b_asm,   a_asm);    // -> g_base16
    }
    {
        dim3 g((kN + 127) / 128, kHW / 128, kB);
        k_gemm1<<<g, 256>>>();                                          // 4th launch (profiled)
    }
    k_invn<<<(kB * kN + 255) / 256, 256>>>();                           // also builds g_tab
    {
        dim3 g(kHW, kB);
        k_softmax<<<g, 256>>>();
    }
    {
        dim3 g((kN + 255) / 256, kHW, kB);
        k_stencilT<<<g, 256>>>();
    }
    {
        dim3 g(kHW / 128, kB);
        k_gemm2<<<g, 256>>>(x, out);
    }
}